// round 4
// baseline (speedup 1.0000x reference)
#include <cuda_runtime.h>
#include <math.h>

// ---------------------------------------------------------------------------
// QNetBlock: 18-qubit state-vector sim, batch 32.
//   state = P2 * D2 * P1 * D1 * x ;  out = |state| / ||x||
// Factorization:  D = Phi_out * (tensor RY) * Phi_in   (Phi diagonal)
//   -> real-coefficient butterflies (8 FMA/pair) + cheap diagonal phase mults.
// Final layer: Phi_out (low+high) dropped — magnitudes are phase-invariant.
// P = CNOT ring = GF(2)-linear permutation (XOR column masks), folded into
// the pass_high store as a scatter. Wire w <-> index bit (17-w).
// ---------------------------------------------------------------------------

#define NB      32
#define NBITS   18
#define NSTATE  (1 << NBITS)      // 262144
#define CHUNK   8192              // 2^13
#define NCHUNK  32                // 2^5

__device__ float2 g_sa[(size_t)NB * NSTATE];   // 64 MB ping
__device__ float2 g_sb[(size_t)NB * NSTATE];   // 64 MB pong
__device__ float  g_partial[NB * NCHUNK];
__device__ float  g_invnorm[NB];

struct PermM { unsigned m[18]; };  // columns of the GF(2)-linear CNOT-ring map

// smem swizzle: conflict-free for all three ownership access patterns
__device__ __forceinline__ int sw(int i) {
    return (i & ~31) | ((i ^ (i >> 5)) & 31);
}

__device__ __forceinline__ float2 cmul(float2 a, float2 b) {
    return make_float2(fmaf(a.x, b.x, -a.y * b.y),
                       fmaf(a.x, b.y,  a.y * b.x));
}

// real RY butterfly: [c, -s; s, c] applied to complex pair (8 flops)
__device__ __forceinline__ void bflyr(float2& A, float2& B, float c, float s) {
    float ax = A.x, ay = A.y, bx = B.x, by = B.y;
    A.x = fmaf(c, ax, -s * bx);  A.y = fmaf(c, ay, -s * by);
    B.x = fmaf(s, ax,  c * bx);  B.y = fmaf(s, ay,  c * by);
}

// ---------------------------------------------------------------------------
// pass_low: one layer's gates on bits 0..12 (wires 5..17).
// CTA = one contiguous 8192-amp chunk. 256 threads x 32 amps in registers.
// Ownership A: bits 8..12 (coalesced global load) -> 5 RY levels
// Ownership B: bits 0..4  (smem transpose)        -> 5 RY levels
// Ownership C: bits 5..9  (smem transpose)        -> RY levels 5..7, store
// Phi_in applied at load (A order), Phi_out at store (C order, if OUTPHASE).
// FIRST: reads float x, emits deterministic per-chunk sum(x^2).
// ---------------------------------------------------------------------------
template<bool FIRST, bool OUTPHASE>
__global__ void __launch_bounds__(256, 2)
pass_low(const float* __restrict__ x, const float* __restrict__ params)
{
    extern __shared__ float2 smem[];     // 8192 float2 = 64 KB
    __shared__ float  cs_[13], sn_[13];  // RY cos/sin per bit
    __shared__ float2 Tin[32];           // e^{i sum bit_j(k) phi_{8+j}}   (bits 8..12)
    __shared__ float2 Tout[32];          // e^{i sum bit_j(k) omega_{5+j}} (bits 5..9)
    __shared__ float  wsum[8];

    int t  = threadIdx.x;
    int b  = blockIdx.x >> 5;
    int ch = blockIdx.x & 31;
    int base = b * NSTATE + ch * CHUNK;

    if (t < 13) {                                   // RY coefficients, bit p = t
        float th = params[(17 - t) * 3 + 1];
        sincosf(0.5f * th, &sn_[t], &cs_[t]);
    } else if (t >= 32 && t < 64) {                 // Tin over bits 8..12
        int k = t - 32; float a = 0.f;
#pragma unroll
        for (int j = 0; j < 5; j++)
            if ((k >> j) & 1) a += params[(17 - (8 + j)) * 3 + 0];
        float s, c; sincosf(a, &s, &c); Tin[k] = make_float2(c, s);
    } else if (t >= 64 && t < 96) {                 // Tout over bits 5..9
        int k = t - 64; float a = 0.f;
#pragma unroll
        for (int j = 0; j < 5; j++)
            if ((k >> j) & 1) a += params[(17 - (5 + j)) * 3 + 2];
        float s, c; sincosf(a, &s, &c); Tout[k] = make_float2(c, s);
    }

    // per-thread Phi_in base phasor: -sum(phi)/2 over all 13 bits, plus
    // +phi_p for each set bit p<8 of t (ownership-A fixed bits)
    float angIn = 0.f;
#pragma unroll
    for (int p = 0; p < 13; p++) {
        float ph = params[(17 - p) * 3 + 0];
        angIn -= 0.5f * ph;
        if (p < 8 && ((t >> p) & 1)) angIn += ph;
    }
    float2 f0; sincosf(angIn, &f0.y, &f0.x);

    float2 v[32];
    if (FIRST) {
        float ss = 0.f;
#pragma unroll
        for (int k = 0; k < 32; k++) {
            float xv = x[base + t + 256 * k];
            v[k] = make_float2(xv, 0.f);
            ss += xv * xv;
        }
#pragma unroll
        for (int o = 16; o; o >>= 1) ss += __shfl_down_sync(0xffffffffu, ss, o);
        if ((t & 31) == 0) wsum[t >> 5] = ss;
    } else {
#pragma unroll
        for (int k = 0; k < 32; k++) v[k] = g_sb[base + t + 256 * k];
    }
    __syncthreads();   // gates, tables, wsum ready
    if (FIRST && t == 0) {
        float s = 0.f;
        for (int i = 0; i < 8; i++) s += wsum[i];
        g_partial[blockIdx.x] = s;   // deterministic fixed-order reduction
    }

    // Phi_in: v[k] *= f0 * Tin[k]   (k = bits 8..12; f0 covers bits 0..7)
#pragma unroll
    for (int k = 0; k < 32; k++) {
        float2 fk = cmul(f0, Tin[k]);
        if (FIRST) v[k] = make_float2(v[k].x * fk.x, v[k].x * fk.y);
        else       v[k] = cmul(v[k], fk);
    }

    // Ownership A: RY on bits 8..12
#pragma unroll
    for (int kb = 0; kb < 5; kb++) {
        int m = 1 << kb;
        float c = cs_[8 + kb], s = sn_[8 + kb];
#pragma unroll
        for (int k = 0; k < 32; k++)
            if (!(k & m)) bflyr(v[k], v[k + m], c, s);
    }
#pragma unroll
    for (int k = 0; k < 32; k++) smem[sw(t + 256 * k)] = v[k];
    __syncthreads();

    // Ownership B: elem = t*32 + k -> RY on bits 0..4
#pragma unroll
    for (int k = 0; k < 32; k++) v[k] = smem[sw(t * 32 + k)];
#pragma unroll
    for (int kb = 0; kb < 5; kb++) {
        int m = 1 << kb;
        float c = cs_[kb], s = sn_[kb];
#pragma unroll
        for (int k = 0; k < 32; k++)
            if (!(k & m)) bflyr(v[k], v[k + m], c, s);
    }
#pragma unroll
    for (int k = 0; k < 32; k++) smem[sw(t * 32 + k)] = v[k];
    __syncthreads();

    // Ownership C: elem = r + 32*k + 1024*h -> RY on bits 5..7
    int r = t & 31, h = t >> 5;
#pragma unroll
    for (int k = 0; k < 32; k++) v[k] = smem[sw(r + 32 * k + 1024 * h)];
#pragma unroll
    for (int kb = 0; kb < 3; kb++) {
        int m = 1 << kb;
        float c = cs_[5 + kb], s = sn_[5 + kb];
#pragma unroll
        for (int k = 0; k < 32; k++)
            if (!(k & m)) bflyr(v[k], v[k + m], c, s);
    }

    if (OUTPHASE) {
        // Phi_out base: fixed bits 0..4 (r) and 10..12 (h); k covers 5..9
        float ango = 0.f;
#pragma unroll
        for (int p = 0; p < 13; p++) {
            float om = params[(17 - p) * 3 + 2];
            ango -= 0.5f * om;
            int bit = (p < 5) ? ((r >> p) & 1)
                    : (p >= 10 ? ((h >> (p - 10)) & 1) : 0);
            if (bit) ango += om;
        }
        float2 fo; sincosf(ango, &fo.y, &fo.x);
#pragma unroll
        for (int k = 0; k < 32; k++) {
            float2 fk = cmul(fo, Tout[k]);
            g_sa[base + r + 32 * k + 1024 * h] = cmul(v[k], fk);
        }
    } else {
#pragma unroll
        for (int k = 0; k < 32; k++)       // coalesced: lanes (r) contiguous
            g_sa[base + r + 32 * k + 1024 * h] = v[k];
    }
}

// ---------------------------------------------------------------------------
// pass_high: one layer's gates on bits 13..17 (wires 0..4), then the CNOT-ring
// permutation folded into the store as an XOR-mask scatter.
// Thread owns 32 amps at stride 2^13 (bits 13..17); lanes = contiguous bits
// 0..4 -> every load is a coalesced 256B warp read. No smem tile.
// Phi_in,hi applied at load; Phi_out,hi applied before store (skip if LAST:
// output magnitudes are invariant to the final diagonal).
// LAST: writes |amp| * invnorm to the float output.
// ---------------------------------------------------------------------------
template<bool LAST>
__global__ void __launch_bounds__(256, 2)
pass_high(const float* __restrict__ params, PermM P, float* __restrict__ outF)
{
    __shared__ float  cs5[5], sn5[5];
    __shared__ float2 Hin[32], Hout[32];
    int t = threadIdx.x;
    if (t < 5) {                                    // gate for bit 13+t = wire 4-t
        float th = params[(4 - t) * 3 + 1];
        sincosf(0.5f * th, &sn5[t], &cs5[t]);
    } else if (t >= 32 && t < 64) {
        int k = t - 32;
        float ai = 0.f, ao = 0.f;
#pragma unroll
        for (int j = 0; j < 5; j++) {
            const float* pp = params + (4 - j) * 3;  // wire for bit 13+j
            float ph = pp[0], om = pp[2];
            ai -= 0.5f * ph;  ao -= 0.5f * om;
            if ((k >> j) & 1) { ai += ph; ao += om; }
        }
        float s, c;
        sincosf(ai, &s, &c); Hin[k]  = make_float2(c, s);
        sincosf(ao, &s, &c); Hout[k] = make_float2(c, s);
    }
    __syncthreads();

    int lane = t & 31, warp = t >> 5;
    int b    = blockIdx.x >> 5;
    int col  = (blockIdx.x & 31) * 8 + warp;   // bits 5..12
    int off  = (col << 5) | lane;              // bits 0..12
    int base = b * NSTATE + off;

    float2 v[32];
#pragma unroll
    for (int k = 0; k < 32; k++)
        v[k] = cmul(g_sa[base + (k << 13)], Hin[k]);   // load + Phi_in,hi

#pragma unroll
    for (int kb = 0; kb < 5; kb++) {
        int m = 1 << kb;
        float c = cs5[kb], s = sn5[kb];
#pragma unroll
        for (int k = 0; k < 32; k++)
            if (!(k & m)) bflyr(v[k], v[k + m], c, s);
    }

    // Permutation target base from low 13 bits (GF(2)-linear -> XOR of columns)
    unsigned tb = 0;
#pragma unroll
    for (int p = 0; p < 13; p++)
        tb ^= P.m[p] & (0u - (unsigned)((off >> p) & 1));
    unsigned m13 = P.m[13], m14 = P.m[14], m15 = P.m[15],
             m16 = P.m[16], m17 = P.m[17];
    int bb = b * NSTATE;

    if (!LAST) {
#pragma unroll
        for (int k = 0; k < 32; k++) {
            unsigned tg = tb;
            if (k & 1)  tg ^= m13;
            if (k & 2)  tg ^= m14;
            if (k & 4)  tg ^= m15;
            if (k & 8)  tg ^= m16;
            if (k & 16) tg ^= m17;
            g_sb[bb + tg] = cmul(v[k], Hout[k]);       // Phi_out,hi then scatter
        }
    } else {
        float inv = g_invnorm[b];
#pragma unroll
        for (int k = 0; k < 32; k++) {
            unsigned tg = tb;
            if (k & 1)  tg ^= m13;
            if (k & 2)  tg ^= m14;
            if (k & 4)  tg ^= m15;
            if (k & 8)  tg ^= m16;
            if (k & 16) tg ^= m17;
            float2 a = v[k];                            // final diagonal dropped
            outF[bb + tg] = sqrtf(a.x * a.x + a.y * a.y) * inv;
        }
    }
}

__global__ void norm_kernel() {
    int b = threadIdx.x;
    if (b < NB) {
        float s = 0.f;
        for (int i = 0; i < NCHUNK; i++) s += g_partial[b * NCHUNK + i];
        g_invnorm[b] = 1.0f / sqrtf(s);
    }
}

// ---------------------------------------------------------------------------
// Host side
// ---------------------------------------------------------------------------
static PermM makePerm(int l) {
    // scatter target = F18(...F1(i)): apply CNOTs in loop order to a basis
    // index. Linear over GF(2) -> precompute columns.
    PermM P;
    for (int p = 0; p < 18; p++) {
        unsigned idx = 1u << p;
        for (int i = 0; i < 18; i++) {
            int c  = (i + l) % 18;
            int t  = (i + l + 1) % 18;
            int cb = 17 - c;
            int tb = 17 - t;
            idx ^= ((idx >> cb) & 1u) << tb;
        }
        P.m[p] = idx;
    }
    return P;
}

extern "C" void kernel_launch(void* const* d_in, const int* in_sizes, int n_in,
                              void* d_out, int out_size)
{
    const float* x      = (const float*)d_in[0];
    const float* params = (const float*)d_in[1];
    if (n_in >= 2 && in_sizes[0] < in_sizes[1]) {  // defensive input-order guard
        x      = (const float*)d_in[1];
        params = (const float*)d_in[0];
    }

    cudaFuncSetAttribute(pass_low<true, true>,
                         cudaFuncAttributeMaxDynamicSharedMemorySize, CHUNK * 8);
    cudaFuncSetAttribute(pass_low<false, false>,
                         cudaFuncAttributeMaxDynamicSharedMemorySize, CHUNK * 8);

    PermM P0 = makePerm(0);
    PermM P1 = makePerm(1);

    // Layer 0 (full gates: Phi_in, RY, Phi_out)
    pass_low<true, true>  <<<NB * NCHUNK, 256, CHUNK * 8>>>(x, params);
    norm_kernel           <<<1, 32>>>();
    pass_high<false>      <<<NB * 32, 256>>>(params, P0, nullptr);
    // Layer 1 (Phi_out dropped everywhere: |.| is phase-invariant)
    pass_low<false, false><<<NB * NCHUNK, 256, CHUNK * 8>>>(nullptr, params + 18 * 3);
    pass_high<true>       <<<NB * 32, 256>>>(params + 18 * 3, P1, (float*)d_out);
}

// round 5
// speedup vs baseline: 1.6287x; 1.6287x over previous
#include <cuda_runtime.h>
#include <math.h>

// ---------------------------------------------------------------------------
// QNetBlock: 18-qubit state-vector sim, batch 32.
//   out = | P2 * D2 * P1 * D1 * x | / ||x||
// Per layer D = Phi_out * (tensor RY) * Phi_in (Phi diagonal, RY real).
// RY butterflies use packed f32x2 (FFMA2/FMUL2): 2 wide instr per amp/level.
// Diagonal placement:
//   pass1: Phi_in,lo(L0) at load; store plain.
//   pass2: [Phi_in,hi(L0) * Phi_out,lo(L0)] at load; Phi_out,hi(L0) at store;
//          then P1 scatter.
//   pass3: Phi_in,lo(L1) at load; in-place (64MB working set, fits L2).
//   pass4: Phi_in,hi(L1) at load; Phi_out(L1) dropped (|.| phase-invariant);
//          P2 scatter + |amp|/||x|| to output.
// P = CNOT ring = GF(2)-linear permutation (XOR column masks).
// Wire w <-> index bit (17-w).
// ---------------------------------------------------------------------------

#define NB      32
#define NBITS   18
#define NSTATE  (1 << NBITS)      // 262144
#define CHUNK   8192              // 2^13
#define NCHUNK  32

typedef unsigned long long u64;

__device__ u64   g_sa[(size_t)NB * NSTATE];   // 64 MB
__device__ u64   g_sb[(size_t)NB * NSTATE];   // 64 MB
__device__ float g_partial[NB * NCHUNK];
__device__ float g_invnorm[NB];

struct PermM { unsigned m[18]; };

// ---- packed f32x2 helpers --------------------------------------------------
__device__ __forceinline__ u64 pk(float x, float y) {
    u64 r; asm("mov.b64 %0,{%1,%2};" : "=l"(r) : "f"(x), "f"(y)); return r;
}
__device__ __forceinline__ void up(u64 a, float& x, float& y) {
    asm("mov.b64 {%0,%1},%2;" : "=f"(x), "=f"(y) : "l"(a));
}
__device__ __forceinline__ u64 f2mul(u64 a, u64 b) {
    u64 r; asm("mul.rn.f32x2 %0,%1,%2;" : "=l"(r) : "l"(a), "l"(b)); return r;
}
__device__ __forceinline__ u64 f2fma(u64 a, u64 b, u64 c) {
    u64 r; asm("fma.rn.f32x2 %0,%1,%2,%3;" : "=l"(r) : "l"(a), "l"(b), "l"(c)); return r;
}
// complex multiply (scalar: packed swap costs movs, no win)
__device__ __forceinline__ u64 cmulp(u64 a, u64 b) {
    float ax, ay, bx, by; up(a, ax, ay); up(b, bx, by);
    return pk(fmaf(ax, bx, -ay * by), fmaf(ax, by, ay * bx));
}
// RY butterfly on packed complex: A' = c*A - s*B ; B' = s*A + c*B
__device__ __forceinline__ void bfly2(u64& A, u64& B, u64 c2, u64 s2, u64 ns2) {
    u64 tA = f2mul(ns2, B);
    u64 tB = f2mul(c2,  B);
    u64 nA = f2fma(c2, A, tA);
    B      = f2fma(s2, A, tB);
    A      = nA;
}

// smem swizzle: conflict-free for all three ownership access patterns
__device__ __forceinline__ int sw(int i) {
    return (i & ~31) | ((i ^ (i >> 5)) & 31);
}

// ---------------------------------------------------------------------------
// pass_low: one layer's RY gates on bits 0..12 + Phi_in,lo at load.
// CTA = contiguous 8192-amp chunk; 256 threads x 32 packed amps.
// Ownership A: bits 8..12 (coalesced) -> 5 levels
// Ownership B: bits 0..4  (smem)      -> 5 levels
// Ownership C: bits 5..9  (smem)      -> levels 5..7, plain store.
// FIRST: reads float x, emits deterministic per-chunk sum(x^2).
// ---------------------------------------------------------------------------
template<bool FIRST>
__global__ void __launch_bounds__(256, 2)
pass_low(const float* __restrict__ x, const float* __restrict__ params,
         u64* __restrict__ dst, const u64* __restrict__ src)
{
    extern __shared__ u64 smem[];          // 8192 u64 = 64 KB
    __shared__ float sp[54];
    __shared__ u64   C2[13], S2[13], NS2[13], Tin[32];
    __shared__ float wsum[8];

    int t  = threadIdx.x;
    int b  = blockIdx.x >> 5;
    int ch = blockIdx.x & 31;
    int base = b * NSTATE + ch * CHUNK;

    // 1) issue state loads first (overlap with setup)
    u64 v[32];
    if (FIRST) {
        float ss = 0.f;
#pragma unroll
        for (int k = 0; k < 32; k++) {
            float xv = x[base + t + 256 * k];
            v[k] = pk(xv, 0.f);
            ss += xv * xv;
        }
#pragma unroll
        for (int o = 16; o; o >>= 1) ss += __shfl_down_sync(0xffffffffu, ss, o);
        if ((t & 31) == 0) wsum[t >> 5] = ss;
    } else {
#pragma unroll
        for (int k = 0; k < 32; k++) v[k] = src[base + t + 256 * k];
    }
    if (t < 54) sp[t] = params[t];
    __syncthreads();                       // sp + wsum ready

    if (FIRST && t == 0) {
        float s = 0.f;
        for (int i = 0; i < 8; i++) s += wsum[i];
        g_partial[blockIdx.x] = s;         // deterministic fixed-order sum
    }

    // 2) tables (from smem params only)
    if (t < 13) {                          // RY coeffs for bit p = t (wire 17-t)
        float s, c; sincosf(0.5f * sp[(17 - t) * 3 + 1], &s, &c);
        C2[t] = pk(c, c); S2[t] = pk(s, s); NS2[t] = pk(-s, -s);
    } else if (t >= 32 && t < 64) {        // Phi_in over k-bits 8..12
        int k = t - 32; float a = 0.f;
#pragma unroll
        for (int j = 0; j < 5; j++)
            if ((k >> j) & 1) a += sp[(17 - (8 + j)) * 3 + 0];
        float s, c; sincosf(a, &s, &c); Tin[k] = pk(c, s);
    }
    // per-thread Phi_in base (bits 0..7 of t, plus global -sum/2)
    float ang = 0.f;
#pragma unroll
    for (int p = 0; p < 13; p++) {
        float ph = sp[(17 - p) * 3 + 0];
        ang -= 0.5f * ph;
        if (p < 8 && ((t >> p) & 1)) ang += ph;
    }
    float fs, fc; sincosf(ang, &fs, &fc);
    u64 pf0 = pk(fc, fs);
    __syncthreads();                       // tables ready

    // 3) Phi_in,lo
#pragma unroll
    for (int k = 0; k < 32; k++)
        v[k] = cmulp(v[k], cmulp(pf0, Tin[k]));

    // 4) ownership A: RY bits 8..12
#pragma unroll
    for (int kb = 0; kb < 5; kb++) {
        int m = 1 << kb;
        u64 c2 = C2[8 + kb], s2 = S2[8 + kb], ns2 = NS2[8 + kb];
#pragma unroll
        for (int k = 0; k < 32; k++)
            if (!(k & m)) bfly2(v[k], v[k + m], c2, s2, ns2);
    }
#pragma unroll
    for (int k = 0; k < 32; k++) smem[sw(t + 256 * k)] = v[k];
    __syncthreads();

    // 5) ownership B: elem = t*32+k, RY bits 0..4
#pragma unroll
    for (int k = 0; k < 32; k++) v[k] = smem[sw(t * 32 + k)];
#pragma unroll
    for (int kb = 0; kb < 5; kb++) {
        int m = 1 << kb;
        u64 c2 = C2[kb], s2 = S2[kb], ns2 = NS2[kb];
#pragma unroll
        for (int k = 0; k < 32; k++)
            if (!(k & m)) bfly2(v[k], v[k + m], c2, s2, ns2);
    }
#pragma unroll
    for (int k = 0; k < 32; k++) smem[sw(t * 32 + k)] = v[k];
    __syncthreads();

    // 6) ownership C: elem = r + 32k + 1024h, RY bits 5..7, plain store
    int r = t & 31, h = t >> 5;
#pragma unroll
    for (int k = 0; k < 32; k++) v[k] = smem[sw(r + 32 * k + 1024 * h)];
#pragma unroll
    for (int kb = 0; kb < 3; kb++) {
        int m = 1 << kb;
        u64 c2 = C2[5 + kb], s2 = S2[5 + kb], ns2 = NS2[5 + kb];
#pragma unroll
        for (int k = 0; k < 32; k++)
            if (!(k & m)) bfly2(v[k], v[k + m], c2, s2, ns2);
    }
#pragma unroll
    for (int k = 0; k < 32; k++)
        dst[base + r + 32 * k + 1024 * h] = v[k];   // coalesced (lanes = r)
}

// ---------------------------------------------------------------------------
// pass_high: one layer's RY gates on bits 13..17, diagonals at load/store,
// CNOT-ring permutation folded into the store as an XOR-mask scatter.
// Thread owns 32 amps at stride 2^13; lanes = contiguous bits 0..4.
//  !LAST (layer 0): load diag = Phi_in,hi(L0)*Phi_out,lo(L0);
//                   store diag = Phi_out,hi(L0); scatter to dst.
//  LAST  (layer 1): load diag = Phi_in,hi(L1); Phi_out dropped;
//                   scatter |amp| * invnorm to float output.
// ---------------------------------------------------------------------------
template<bool LAST>
__global__ void __launch_bounds__(256, 2)
pass_high(const float* __restrict__ params, PermM P,
          const u64* __restrict__ src, u64* __restrict__ dst,
          float* __restrict__ outF)
{
    __shared__ float sp[54];
    __shared__ u64   C2[5], S2[5], NS2[5], Hin[32], Hout[32];

    int t    = threadIdx.x;
    int lane = t & 31, warp = t >> 5;
    int b    = blockIdx.x >> 5;
    int col  = (blockIdx.x & 31) * 8 + warp;   // bits 5..12
    int off  = (col << 5) | lane;              // bits 0..12
    int base = b * NSTATE + off;

    // 1) state loads first (coalesced 256B per warp-load)
    u64 v[32];
#pragma unroll
    for (int k = 0; k < 32; k++) v[k] = src[base + (k << 13)];

    if (t < 54) sp[t] = params[t];
    __syncthreads();

    // 2) tables
    if (t < 5) {                                // RY for bit 13+t = wire 4-t
        float s, c; sincosf(0.5f * sp[(4 - t) * 3 + 1], &s, &c);
        C2[t] = pk(c, c); S2[t] = pk(s, s); NS2[t] = pk(-s, -s);
    } else if (t >= 32 && t < 64) {
        int k = t - 32;
        float ai = 0.f, ao = 0.f;
#pragma unroll
        for (int j = 0; j < 5; j++) {
            float ph = sp[(4 - j) * 3 + 0];
            float om = sp[(4 - j) * 3 + 2];
            ai -= 0.5f * ph;  ao -= 0.5f * om;
            if ((k >> j) & 1) { ai += ph; ao += om; }
        }
        float s, c;
        sincosf(ai, &s, &c); Hin[k] = pk(c, s);
        if (!LAST) { sincosf(ao, &s, &c); Hout[k] = pk(c, s); }
    }
    // per-thread g = Phi_out,lo(L0) over off bits (only for !LAST)
    u64 pg = pk(1.f, 0.f);
    if (!LAST) {
        float ang = 0.f;
#pragma unroll
        for (int p = 0; p < 13; p++) {
            float om = sp[(17 - p) * 3 + 2];
            ang -= 0.5f * om;
            if ((off >> p) & 1) ang += om;
        }
        float s, c; sincosf(ang, &s, &c); pg = pk(c, s);
    }
    __syncthreads();

    // 3) load diagonal
#pragma unroll
    for (int k = 0; k < 32; k++)
        v[k] = cmulp(v[k], LAST ? Hin[k] : cmulp(pg, Hin[k]));

    // 4) RY bits 13..17
#pragma unroll
    for (int kb = 0; kb < 5; kb++) {
        int m = 1 << kb;
        u64 c2 = C2[kb], s2 = S2[kb], ns2 = NS2[kb];
#pragma unroll
        for (int k = 0; k < 32; k++)
            if (!(k & m)) bfly2(v[k], v[k + m], c2, s2, ns2);
    }

    // 5) permutation target base (GF(2)-linear -> XOR of columns)
    unsigned tb = 0;
#pragma unroll
    for (int p = 0; p < 13; p++)
        tb ^= P.m[p] & (0u - (unsigned)((off >> p) & 1));
    unsigned m13 = P.m[13], m14 = P.m[14], m15 = P.m[15],
             m16 = P.m[16], m17 = P.m[17];
    int bb = b * NSTATE;

    if (!LAST) {
#pragma unroll
        for (int k = 0; k < 32; k++) {
            unsigned tg = tb;
            if (k & 1)  tg ^= m13;
            if (k & 2)  tg ^= m14;
            if (k & 4)  tg ^= m15;
            if (k & 8)  tg ^= m16;
            if (k & 16) tg ^= m17;
            dst[bb + tg] = cmulp(v[k], Hout[k]);   // Phi_out,hi then scatter
        }
    } else {
        float inv = g_invnorm[b];
#pragma unroll
        for (int k = 0; k < 32; k++) {
            unsigned tg = tb;
            if (k & 1)  tg ^= m13;
            if (k & 2)  tg ^= m14;
            if (k & 4)  tg ^= m15;
            if (k & 8)  tg ^= m16;
            if (k & 16) tg ^= m17;
            float ax, ay; up(v[k], ax, ay);
            outF[bb + tg] = sqrtf(fmaf(ax, ax, ay * ay)) * inv;
        }
    }
}

__global__ void norm_kernel() {
    int b = threadIdx.x;
    if (b < NB) {
        float s = 0.f;
        for (int i = 0; i < NCHUNK; i++) s += g_partial[b * NCHUNK + i];
        g_invnorm[b] = 1.0f / sqrtf(s);
    }
}

// ---------------------------------------------------------------------------
// Host side
// ---------------------------------------------------------------------------
static PermM makePerm(int l) {
    PermM P;
    for (int p = 0; p < 18; p++) {
        unsigned idx = 1u << p;
        for (int i = 0; i < 18; i++) {
            int c  = (i + l) % 18;
            int t  = (i + l + 1) % 18;
            int cb = 17 - c;
            int tb = 17 - t;
            idx ^= ((idx >> cb) & 1u) << tb;
        }
        P.m[p] = idx;
    }
    return P;
}

extern "C" void kernel_launch(void* const* d_in, const int* in_sizes, int n_in,
                              void* d_out, int out_size)
{
    const float* x      = (const float*)d_in[0];
    const float* params = (const float*)d_in[1];
    if (n_in >= 2 && in_sizes[0] < in_sizes[1]) {  // defensive input-order guard
        x      = (const float*)d_in[1];
        params = (const float*)d_in[0];
    }

    cudaFuncSetAttribute(pass_low<true>,
                         cudaFuncAttributeMaxDynamicSharedMemorySize, CHUNK * 8);
    cudaFuncSetAttribute(pass_low<false>,
                         cudaFuncAttributeMaxDynamicSharedMemorySize, CHUNK * 8);

    PermM P0 = makePerm(0);
    PermM P1 = makePerm(1);

    u64* sa = nullptr; u64* sb = nullptr;
    cudaGetSymbolAddress((void**)&sa, g_sa);
    cudaGetSymbolAddress((void**)&sb, g_sb);

    // Layer 0
    pass_low<true>  <<<NB * NCHUNK, 256, CHUNK * 8>>>(x, params, sa, nullptr);
    norm_kernel     <<<1, 32>>>();
    pass_high<false><<<NB * 32, 256>>>(params, P0, sa, sb, nullptr);
    // Layer 1 (pass3 in-place: 64MB working set fits L2)
    pass_low<false> <<<NB * NCHUNK, 256, CHUNK * 8>>>(nullptr, params + 54, sb, sb);
    pass_high<true> <<<NB * 32, 256>>>(params + 54, P1, sb, nullptr, (float*)d_out);
}